// round 6
// baseline (speedup 1.0000x reference)
#include <cuda_runtime.h>

typedef unsigned long long u64;

static constexpr int Bb = 16;
static constexpr int CE = 1024;
static constexpr int Tt = 2048;
static constexpr int CC = 64;
static constexpr int Kk = 4096;

static constexpr long long O_CODES = 0;
static constexpr long long O_QUANT = 32768;
static constexpr long long N_QUANT = (long long)Bb * CE * Tt;    // 33554432
static constexpr long long O_CBL   = O_QUANT + N_QUANT;           // 33587200
static constexpr long long O_CML   = O_CBL + 1;
static constexpr long long O_XPROJ = O_CML + 1;                   // 33587202 (even -> 8B aligned)
static constexpr long long N_XP    = (long long)Bb * CC * Tt;     // 2097152
static constexpr long long O_QPROJ = O_XPROJ + N_XP;              // 35684354 (even)

// scratch (static device globals; no runtime allocation)
__device__ __align__(16) float  g_Win[CC * CE];
__device__ __align__(16) float  g_Wout[CE * CC];
__device__ __align__(16) float  g_cbT[CC * Kk];    // (-2 * normalized codebook), transposed [o][k]
__device__ __align__(16) float  g_cbn2[Kk];        // ||cb_n||^2
__device__ double g_lpart[512];

__device__ __forceinline__ u64 pk2(float lo, float hi) {
    u64 r; asm("mov.b64 %0, {%1, %2};" : "=l"(r) : "f"(lo), "f"(hi)); return r;
}
__device__ __forceinline__ float2 upk2(u64 v) {
    float2 r; asm("mov.b64 {%0, %1}, %2;" : "=f"(r.x), "=f"(r.y) : "l"(v)); return r;
}
__device__ __forceinline__ void fma2(u64 &d, u64 a, u64 b) {
    asm("fma.rn.f32x2 %0, %1, %2, %0;" : "+l"(d) : "l"(a), "l"(b));
}

// ---------------- prep: weight-norm W_in (rows of 1024) ----------------
__global__ __launch_bounds__(256) void k_prep_win(const float* __restrict__ v_in,
                                                  const float* __restrict__ g_in)
{
    __shared__ float sb[256];
    __shared__ float snorm;
    int o = blockIdx.x, tid = threadIdx.x;
    float s = 0.f;
#pragma unroll
    for (int j = 0; j < 4; j++) { float v = v_in[o * CE + tid + j * 256]; s += v * v; }
    sb[tid] = s; __syncthreads();
    for (int off = 128; off > 0; off >>= 1) { if (tid < off) sb[tid] += sb[tid + off]; __syncthreads(); }
    if (tid == 0) snorm = __fsqrt_rn(sb[0]);
    __syncthreads();
    float n = snorm, g = g_in[o];
#pragma unroll
    for (int j = 0; j < 4; j++) {
        int i = tid + j * 256;
        g_Win[o * CE + i] = __fdiv_rn(g * v_in[o * CE + i], n);
    }
}

// ---------------- prep: weight-norm W_out (rows of 64), warp/row ----------------
__global__ __launch_bounds__(256) void k_prep_wout(const float* __restrict__ v_out,
                                                   const float* __restrict__ g_out)
{
    int gw = (blockIdx.x * 256 + threadIdx.x) >> 5;
    int l = threadIdx.x & 31;
    float a = v_out[gw * CC + l], b = v_out[gw * CC + l + 32];
    float s = a * a + b * b;
#pragma unroll
    for (int off = 16; off; off >>= 1) s += __shfl_xor_sync(0xffffffffu, s, off);
    float n = __fsqrt_rn(s), g = g_out[gw];
    g_Wout[gw * CC + l]      = __fdiv_rn(g * a, n);
    g_Wout[gw * CC + l + 32] = __fdiv_rn(g * b, n);
}

// ---------------- prep: normalize codebook -> (-2x) transposed + ||.||^2 ----------------
__global__ __launch_bounds__(256) void k_prep_cb(const float* __restrict__ cb)
{
    int k = (blockIdx.x * 256 + threadIdx.x) >> 5;
    int l = threadIdx.x & 31;
    float a = cb[k * CC + l], b = cb[k * CC + l + 32];
    float s = a * a + b * b;
#pragma unroll
    for (int off = 16; off; off >>= 1) s += __shfl_xor_sync(0xffffffffu, s, off);
    float n = fmaxf(__fsqrt_rn(s), 1e-12f);
    float ca = __fdiv_rn(a, n), cbv = __fdiv_rn(b, n);
    g_cbT[l * Kk + k]        = -2.f * ca;
    g_cbT[(l + 32) * Kk + k] = -2.f * cbv;
    float s2 = ca * ca + cbv * cbv;
#pragma unroll
    for (int off = 16; off; off >>= 1) s2 += __shfl_xor_sync(0xffffffffu, s2, off);
    if (l == 0) g_cbn2[k] = s2;
}

// ---------------- x_proj = W_in @ x ----------------
// block = 64 o x 256 t, 256 threads, thread = 4 o x 16 t (4 strided float4 groups).
// W duplicated in smem -> all FFMA2 operands loaded directly as u64 (no packing).
static constexpr int XS_STRIDE = 260;   // 32 x 260 floats
static constexpr int WS_STRIDE = 132;   // 32 x 132 floats (dup: 128 used)
static constexpr int SMEM_XPROJ = (32 * XS_STRIDE + 32 * WS_STRIDE) * 4;  // 50176 B

__global__ __launch_bounds__(256) void k_xproj(const float* __restrict__ x,
                                               float* __restrict__ out)
{
    extern __shared__ float sm[];
    float* Xs  = sm;                    // [32][260]
    float* Ws2 = sm + 32 * XS_STRIDE;   // [32][132]
    int b = blockIdx.y, tid = threadIdx.x;
    long long t0 = (long long)blockIdx.x * 256;
    int to = tid >> 4, tt = tid & 15;
    const float* Xp = x + (long long)b * CE * Tt;

    u64 acc[4][8];
#pragma unroll
    for (int i = 0; i < 4; i++)
#pragma unroll
        for (int j = 0; j < 8; j++) acc[i][j] = 0ull;

    for (int kc = 0; kc < CE; kc += 32) {
#pragma unroll
        for (int it = 0; it < 2; it++) {
            int rr = tid + it * 256;                 // 512: 64 o x 8 kq
            int o = rr >> 3, kq = rr & 7;
            float4 w = *(const float4*)&g_Win[o * CE + kc + kq * 4];
            *(u64*)&Ws2[(kq * 4 + 0) * WS_STRIDE + o * 2] = pk2(w.x, w.x);
            *(u64*)&Ws2[(kq * 4 + 1) * WS_STRIDE + o * 2] = pk2(w.y, w.y);
            *(u64*)&Ws2[(kq * 4 + 2) * WS_STRIDE + o * 2] = pk2(w.z, w.z);
            *(u64*)&Ws2[(kq * 4 + 3) * WS_STRIDE + o * 2] = pk2(w.w, w.w);
        }
#pragma unroll
        for (int it = 0; it < 8; it++) {
            int rr = tid + it * 256;                 // 2048 quads: 32 k x 64 t4
            int i = rr >> 6, t4 = rr & 63;
            *(float4*)&Xs[i * XS_STRIDE + t4 * 4] =
                *(const float4*)&Xp[(long long)(kc + i) * Tt + t0 + t4 * 4];
        }
        __syncthreads();
#pragma unroll 8
        for (int k = 0; k < 32; k++) {
            const u64* wp = (const u64*)&Ws2[k * WS_STRIDE + to * 8];
            u64 w0 = wp[0], w1 = wp[1], w2 = wp[2], w3 = wp[3];
#pragma unroll
            for (int g = 0; g < 4; g++) {
                const u64* xp = (const u64*)&Xs[k * XS_STRIDE + g * 64 + tt * 4];
                u64 xa = xp[0], xb = xp[1];
                fma2(acc[0][g * 2], w0, xa); fma2(acc[0][g * 2 + 1], w0, xb);
                fma2(acc[1][g * 2], w1, xa); fma2(acc[1][g * 2 + 1], w1, xb);
                fma2(acc[2][g * 2], w2, xa); fma2(acc[2][g * 2 + 1], w2, xb);
                fma2(acc[3][g * 2], w3, xa); fma2(acc[3][g * 2 + 1], w3, xb);
            }
        }
        __syncthreads();
    }
    float* Op = out + O_XPROJ + (long long)b * CC * Tt + t0;
#pragma unroll
    for (int oj = 0; oj < 4; oj++) {
        long long rb = (long long)(to * 4 + oj) * Tt;
#pragma unroll
        for (int g = 0; g < 4; g++) {
            *(u64*)&Op[rb + g * 64 + tt * 4]     = acc[oj][g * 2];
            *(u64*)&Op[rb + g * 64 + tt * 4 + 2] = acc[oj][g * 2 + 1];
        }
    }
}

// ---------------- quantized = W_out @ quantized_proj ----------------
// block = 128 o x 128 t, 256 threads, thread = 8 o x 8 t. K = 64.
static constexpr int WXS_STRIDE = 132;  // X: 32 x 132
static constexpr int WWS_STRIDE = 260;  // Wdup: 32 x 260
static constexpr int SMEM_WOUT = (32 * WXS_STRIDE + 32 * WWS_STRIDE) * 4;  // 50176 B

__global__ __launch_bounds__(256) void k_wout(float* __restrict__ out)
{
    extern __shared__ float sm[];
    float* Xs  = sm;                      // [32][132]
    float* Ws2 = sm + 32 * WXS_STRIDE;    // [32][260]
    int tid = threadIdx.x;
    int b = blockIdx.y, ob = blockIdx.z;
    long long t0 = (long long)blockIdx.x * 128;
    int to = tid >> 4, tt = tid & 15;
    const float* Xp = out + O_QPROJ + (long long)b * CC * Tt;   // 8B-aligned region
    const float* Wp = g_Wout + (long long)ob * 128 * CC;

    u64 acc[8][4];
#pragma unroll
    for (int i = 0; i < 8; i++)
#pragma unroll
        for (int j = 0; j < 4; j++) acc[i][j] = 0ull;

#pragma unroll
    for (int kc = 0; kc < CC; kc += 32) {
#pragma unroll
        for (int it = 0; it < 4; it++) {
            int rr = tid + it * 256;                 // 1024: 128 o x 8 kq
            int o = rr >> 3, kq = rr & 7;
            float4 w = *(const float4*)&Wp[o * CC + kc + kq * 4];
            *(u64*)&Ws2[(kq * 4 + 0) * WWS_STRIDE + o * 2] = pk2(w.x, w.x);
            *(u64*)&Ws2[(kq * 4 + 1) * WWS_STRIDE + o * 2] = pk2(w.y, w.y);
            *(u64*)&Ws2[(kq * 4 + 2) * WWS_STRIDE + o * 2] = pk2(w.z, w.z);
            *(u64*)&Ws2[(kq * 4 + 3) * WWS_STRIDE + o * 2] = pk2(w.w, w.w);
        }
#pragma unroll
        for (int it = 0; it < 8; it++) {
            int rr = tid + it * 256;                 // 2048 u64: 32 k x 64 t2
            int i = rr >> 6, t2 = rr & 63;
            *(u64*)&Xs[i * WXS_STRIDE + t2 * 2] =
                *(const u64*)&Xp[(long long)(kc + i) * Tt + t0 + t2 * 2];
        }
        __syncthreads();
#pragma unroll 8
        for (int k = 0; k < 32; k++) {
            const u64* wp = (const u64*)&Ws2[k * WWS_STRIDE + to * 16];
            const u64* xp0 = (const u64*)&Xs[k * WXS_STRIDE + tt * 4];
            const u64* xp1 = (const u64*)&Xs[k * WXS_STRIDE + 64 + tt * 4];
            u64 xa = xp0[0], xb = xp0[1], xc = xp1[0], xd = xp1[1];
#pragma unroll
            for (int oj = 0; oj < 8; oj++) {
                u64 w = wp[oj];
                fma2(acc[oj][0], w, xa); fma2(acc[oj][1], w, xb);
                fma2(acc[oj][2], w, xc); fma2(acc[oj][3], w, xd);
            }
        }
        __syncthreads();
    }
    float* Op = out + O_QUANT + (long long)b * CE * Tt + (long long)ob * 128 * Tt + t0;
#pragma unroll
    for (int oj = 0; oj < 8; oj++) {
        long long rb = (long long)(to * 8 + oj) * Tt;
        *(u64*)&Op[rb + tt * 4]          = acc[oj][0];
        *(u64*)&Op[rb + tt * 4 + 2]      = acc[oj][1];
        *(u64*)&Op[rb + 64 + tt * 4]     = acc[oj][2];
        *(u64*)&Op[rb + 64 + tt * 4 + 2] = acc[oj][3];
    }
}

// ---------------- dist + argmin + gather + qproj + loss partials ----------------
// block = 64 t; scans all 4096 codes in chunks of 128. thread = 4 t x 8 k.
// Es duplicated in smem; cbT pre-scaled by -2; acc initialized from ||cb_n||^2
// -> accumulator IS the score. Strict-< ascending-k keeps first min.
static constexpr int ES_STRIDE = 132;   // 64 x 132 (dup t)
static constexpr int CS_STRIDE = 136;   // 64 x 136
static constexpr int SMEM_DIST = (64 * ES_STRIDE + 64 * CS_STRIDE + 128 + 64 + 64) * 4;  // 69632 B

__global__ __launch_bounds__(256) void k_dist(const float* __restrict__ cb,
                                              float* __restrict__ out)
{
    extern __shared__ float sm[];
    float* Es2   = sm;                          // [64][132] dup
    float* Cs    = sm + 64 * ES_STRIDE;         // [64][136]
    float* cbn2s = Cs + 64 * CS_STRIDE;         // [128]
    float* den   = cbn2s + 128;                 // [64]
    int*   scode = (int*)(den + 64);            // [64]
    float* redv  = Es2;                         // overlap (post-chunk only)
    int*   redi  = (int*)(Es2 + 1024);

    int b = blockIdx.y, tid = threadIdx.x;
    long long t0 = (long long)blockIdx.x * 64;
    int tx = tid & 15, ty = tid >> 4;
    const long long xbase = O_XPROJ + (long long)b * (CC * Tt) + t0;

    // stage plain x_proj tile into Cs (free until chunk loop)
#pragma unroll
    for (int it = 0; it < 8; it++) {
        int rr = tid + it * 256;                // 2048 u64: 64 o x 32 t2
        int o = rr >> 5, t2 = rr & 31;
        *(u64*)&Cs[o * CS_STRIDE + t2 * 2] = *(const u64*)&out[xbase + (long long)o * Tt + t2 * 2];
    }
    __syncthreads();
    if (tid < 64) {
        float s = 0.f;
#pragma unroll 8
        for (int o = 0; o < 64; o++) { float v = Cs[o * CS_STRIDE + tid]; s += v * v; }
        den[tid] = fmaxf(__fsqrt_rn(s), 1e-12f);
    }
    __syncthreads();
#pragma unroll
    for (int it = 0; it < 8; it++) {
        int rr = tid + it * 256;
        int o = rr >> 5, t2 = rr & 31;
        float2 v = upk2(*(const u64*)&Cs[o * CS_STRIDE + t2 * 2]);
        float e0 = __fdiv_rn(v.x, den[t2 * 2]);
        float e1 = __fdiv_rn(v.y, den[t2 * 2 + 1]);
        *(u64*)&Es2[o * ES_STRIDE + t2 * 4]     = pk2(e0, e0);
        *(u64*)&Es2[o * ES_STRIDE + t2 * 4 + 2] = pk2(e1, e1);
    }

    float bval[4]; int bidx[4];
#pragma unroll
    for (int i = 0; i < 4; i++) { bval[i] = 3.4028235e38f; bidx[i] = 0; }

    for (int ch = 0; ch < 32; ch++) {
        int kc0 = ch * 128;
        __syncthreads();                        // Es2/Cs ready; prior chunk reads done
#pragma unroll
        for (int it = 0; it < 8; it++) {
            int rr = tid + it * 256;            // 2048 quads: 64 o x 32 k4
            int o = rr >> 5, k4 = rr & 31;
            *(float4*)&Cs[o * CS_STRIDE + k4 * 4] = *(const float4*)&g_cbT[o * Kk + kc0 + k4 * 4];
        }
        if (tid < 128) cbn2s[tid] = g_cbn2[kc0 + tid];
        __syncthreads();

        const u64* ip0 = (const u64*)&cbn2s[tx * 4];
        const u64* ip1 = (const u64*)&cbn2s[64 + tx * 4];
        u64 i0 = ip0[0], i1 = ip0[1], i2 = ip1[0], i3 = ip1[1];
        u64 acc[4][4];
#pragma unroll
        for (int tl = 0; tl < 4; tl++) { acc[tl][0] = i0; acc[tl][1] = i1; acc[tl][2] = i2; acc[tl][3] = i3; }

#pragma unroll 8
        for (int o = 0; o < 64; o++) {
            const u64* ep = (const u64*)&Es2[o * ES_STRIDE + ty * 8];
            u64 e0 = ep[0], e1 = ep[1], e2 = ep[2], e3 = ep[3];
            const u64* cp0 = (const u64*)&Cs[o * CS_STRIDE + tx * 4];
            const u64* cp1 = (const u64*)&Cs[o * CS_STRIDE + 64 + tx * 4];
            u64 c0 = cp0[0], c1 = cp0[1], c2 = cp1[0], c3 = cp1[1];
            fma2(acc[0][0], e0, c0); fma2(acc[0][1], e0, c1); fma2(acc[0][2], e0, c2); fma2(acc[0][3], e0, c3);
            fma2(acc[1][0], e1, c0); fma2(acc[1][1], e1, c1); fma2(acc[1][2], e1, c2); fma2(acc[1][3], e1, c3);
            fma2(acc[2][0], e2, c0); fma2(acc[2][1], e2, c1); fma2(acc[2][2], e2, c2); fma2(acc[2][3], e2, c3);
            fma2(acc[3][0], e3, c0); fma2(acc[3][1], e3, c1); fma2(acc[3][2], e3, c2); fma2(acc[3][3], e3, c3);
        }
#pragma unroll
        for (int tl = 0; tl < 4; tl++) {
#pragma unroll
            for (int j = 0; j < 4; j++) {
                float2 d = upk2(acc[tl][j]);
                int kg = kc0 + ((j >> 1) * 64) + tx * 4 + (j & 1) * 2;
                if (d.x < bval[tl]) { bval[tl] = d.x; bidx[tl] = kg; }
                if (d.y < bval[tl]) { bval[tl] = d.y; bidx[tl] = kg + 1; }
            }
        }
    }
    __syncthreads();                            // all Es2 reads done before redv overlap
#pragma unroll
    for (int tl = 0; tl < 4; tl++) {
        redv[(ty * 4 + tl) * 16 + tx] = bval[tl];
        redi[(ty * 4 + tl) * 16 + tx] = bidx[tl];
    }
    __syncthreads();
    if (tid < 64) {
        float bv = 3.4028235e38f; int bi = 0x7fffffff;
#pragma unroll
        for (int j = 0; j < 16; j++) {
            float v = redv[tid * 16 + j]; int i = redi[tid * 16 + j];
            if (v < bv || (v == bv && i < bi)) { bv = v; bi = i; }
        }
        scode[tid] = bi;
        out[O_CODES + (long long)b * Tt + t0 + tid] = (float)bi;
    }
    __syncthreads();

    // gather q, write quantized_proj = xp + (q - xp), accumulate loss
    {
        int t = tid & 63, og = tid >> 6;
        int code = scode[t];
        const float* cbrow = cb + (long long)code * CC + og * 16;
        long long xb2 = O_XPROJ + (long long)b * (CC * Tt) + t0 + t;
        long long qb2 = O_QPROJ + (long long)b * (CC * Tt) + t0 + t;
        float ls = 0.f;
#pragma unroll
        for (int j = 0; j < 16; j++) {
            long long ro = (long long)(og * 16 + j) * Tt;
            float xp = out[xb2 + ro];
            float q  = cbrow[j];
            float d  = q - xp;
            out[qb2 + ro] = xp + d;
            ls += d * d;
        }
        __syncthreads();
        redv[tid] = ls; __syncthreads();
        for (int off = 128; off > 0; off >>= 1) {
            if (tid < off) redv[tid] += redv[tid + off];
            __syncthreads();
        }
        if (tid == 0) g_lpart[blockIdx.y * gridDim.x + blockIdx.x] = (double)redv[0];
    }
}

// ---------------- final loss reduction ----------------
__global__ __launch_bounds__(512) void k_loss(float* __restrict__ out)
{
    __shared__ double sb[512];
    int tid = threadIdx.x;
    sb[tid] = g_lpart[tid];
    __syncthreads();
    for (int off = 256; off > 0; off >>= 1) {
        if (tid < off) sb[tid] += sb[tid + off];
        __syncthreads();
    }
    if (tid == 0) {
        float l = (float)(sb[0] / (double)(16.0 * 64.0 * 2048.0));
        out[O_CBL] = l;
        out[O_CML] = l;
    }
}

extern "C" void kernel_launch(void* const* d_in, const int* in_sizes, int n_in,
                              void* d_out, int out_size) {
    (void)in_sizes; (void)n_in; (void)out_size;
    const float* x    = (const float*)d_in[0];
    const float* v_in = (const float*)d_in[1];
    const float* g_in = (const float*)d_in[2];
    const float* v_out= (const float*)d_in[3];
    const float* g_out= (const float*)d_in[4];
    const float* cb   = (const float*)d_in[5];
    float* out = (float*)d_out;

    cudaFuncSetAttribute(k_xproj, cudaFuncAttributeMaxDynamicSharedMemorySize, SMEM_XPROJ);
    cudaFuncSetAttribute(k_wout,  cudaFuncAttributeMaxDynamicSharedMemorySize, SMEM_WOUT);
    cudaFuncSetAttribute(k_dist,  cudaFuncAttributeMaxDynamicSharedMemorySize, SMEM_DIST);

    k_prep_win<<<64, 256>>>(v_in, g_in);
    k_prep_wout<<<128, 256>>>(v_out, g_out);
    k_prep_cb<<<512, 256>>>(cb);

    // x_proj = W_in @ x : grid 8 t-tiles x 16 b = 128 blocks (single wave)
    k_xproj<<<dim3(8, 16), 256, SMEM_XPROJ>>>(x, out);

    // codes / qproj / loss partials
    k_dist<<<dim3(32, 16), 256, SMEM_DIST>>>(cb, out);
    k_loss<<<1, 512>>>(out);

    // quantized = W_out @ quantized_proj : grid 16 t x 16 b x 8 o-blocks
    k_wout<<<dim3(16, 16, 8), 256, SMEM_WOUT>>>(out);
}

// round 7
// speedup vs baseline: 1.0563x; 1.0563x over previous
#include <cuda_runtime.h>

typedef unsigned long long u64;

static constexpr int Bb = 16;
static constexpr int CE = 1024;
static constexpr int Tt = 2048;
static constexpr int CC = 64;
static constexpr int Kk = 4096;

static constexpr long long O_CODES = 0;
static constexpr long long O_QUANT = 32768;
static constexpr long long N_QUANT = (long long)Bb * CE * Tt;    // 33554432
static constexpr long long O_CBL   = O_QUANT + N_QUANT;           // 33587200
static constexpr long long O_CML   = O_CBL + 1;
static constexpr long long O_XPROJ = O_CML + 1;                   // 33587202 (even -> 8B aligned)
static constexpr long long N_XP    = (long long)Bb * CC * Tt;     // 2097152
static constexpr long long O_QPROJ = O_XPROJ + N_XP;              // 35684354 (even)

// scratch (static device globals; no runtime allocation)
__device__ __align__(16) float  g_Win[CC * CE];
__device__ __align__(16) float  g_Wout[CE * CC];
__device__ __align__(16) float  g_cbT[CC * Kk];    // (-2 * normalized codebook), transposed [o][k]
__device__ __align__(16) float  g_cbn2[Kk];        // ||cb_n||^2
__device__ double g_lpart[512];

__device__ __forceinline__ u64 pk2(float lo, float hi) {
    u64 r; asm("mov.b64 %0, {%1, %2};" : "=l"(r) : "f"(lo), "f"(hi)); return r;
}
__device__ __forceinline__ float2 upk2(u64 v) {
    float2 r; asm("mov.b64 {%0, %1}, %2;" : "=f"(r.x), "=f"(r.y) : "l"(v)); return r;
}
__device__ __forceinline__ void fma2(u64 &d, u64 a, u64 b) {
    asm("fma.rn.f32x2 %0, %1, %2, %0;" : "+l"(d) : "l"(a), "l"(b));
}

// ---------------- prep: weight-norm W_in (rows of 1024) ----------------
__global__ __launch_bounds__(256) void k_prep_win(const float* __restrict__ v_in,
                                                  const float* __restrict__ g_in)
{
    __shared__ float sb[256];
    __shared__ float snorm;
    int o = blockIdx.x, tid = threadIdx.x;
    float s = 0.f;
#pragma unroll
    for (int j = 0; j < 4; j++) { float v = v_in[o * CE + tid + j * 256]; s += v * v; }
    sb[tid] = s; __syncthreads();
    for (int off = 128; off > 0; off >>= 1) { if (tid < off) sb[tid] += sb[tid + off]; __syncthreads(); }
    if (tid == 0) snorm = __fsqrt_rn(sb[0]);
    __syncthreads();
    float n = snorm, g = g_in[o];
#pragma unroll
    for (int j = 0; j < 4; j++) {
        int i = tid + j * 256;
        g_Win[o * CE + i] = __fdiv_rn(g * v_in[o * CE + i], n);
    }
}

// ---------------- prep: weight-norm W_out (rows of 64), warp/row ----------------
__global__ __launch_bounds__(256) void k_prep_wout(const float* __restrict__ v_out,
                                                   const float* __restrict__ g_out)
{
    int gw = (blockIdx.x * 256 + threadIdx.x) >> 5;
    int l = threadIdx.x & 31;
    float a = v_out[gw * CC + l], b = v_out[gw * CC + l + 32];
    float s = a * a + b * b;
#pragma unroll
    for (int off = 16; off; off >>= 1) s += __shfl_xor_sync(0xffffffffu, s, off);
    float n = __fsqrt_rn(s), g = g_out[gw];
    g_Wout[gw * CC + l]      = __fdiv_rn(g * a, n);
    g_Wout[gw * CC + l + 32] = __fdiv_rn(g * b, n);
}

// ---------------- prep: normalize codebook -> (-2x) transposed + ||.||^2 ----------------
__global__ __launch_bounds__(256) void k_prep_cb(const float* __restrict__ cb)
{
    int k = (blockIdx.x * 256 + threadIdx.x) >> 5;
    int l = threadIdx.x & 31;
    float a = cb[k * CC + l], b = cb[k * CC + l + 32];
    float s = a * a + b * b;
#pragma unroll
    for (int off = 16; off; off >>= 1) s += __shfl_xor_sync(0xffffffffu, s, off);
    float n = fmaxf(__fsqrt_rn(s), 1e-12f);
    float ca = __fdiv_rn(a, n), cbv = __fdiv_rn(b, n);
    g_cbT[l * Kk + k]        = -2.f * ca;
    g_cbT[(l + 32) * Kk + k] = -2.f * cbv;
    float s2 = ca * ca + cbv * cbv;
#pragma unroll
    for (int off = 16; off; off >>= 1) s2 += __shfl_xor_sync(0xffffffffu, s2, off);
    if (l == 0) g_cbn2[k] = s2;
}

// ---------------- Out[64 x 128t] = W[64 x K] @ X[K x 128t] ----------------
// 256 threads, thread = 8 o x 4 t. Warp <-> one 8-o group, so the duplicated
// W operand is a warp-BROADCAST smem read (crossbar-free); X is one
// lane-consecutive LDS.128. Smem demand ~68 B/cyc/SM << 128 cap.
static constexpr int GS = 132;   // row stride for both tiles

template<bool XALN16>
__global__ __launch_bounds__(256) void k_gemm(const float* __restrict__ W, int K, long long WzS,
                                              const float* __restrict__ X, long long XyS,
                                              float* __restrict__ O, long long OyS, long long OzS)
{
    __shared__ __align__(16) float Xs[32 * GS];
    __shared__ __align__(16) float Ws2[32 * GS];   // dup: [k][o*2]
    const float* Wp = W + (long long)blockIdx.z * WzS;
    const float* Xp = X + (long long)blockIdx.y * XyS;
    float* Op = O + (long long)blockIdx.y * OyS + (long long)blockIdx.z * OzS + (long long)blockIdx.x * 128;
    int tid = threadIdx.x;
    int to = tid >> 5;          // 0..7 : o-group of 8 (constant per warp)
    int t4 = tid & 31;          // 0..31 : t-slot of 4
    long long t0 = (long long)blockIdx.x * 128;

    u64 acc[8][2];
#pragma unroll
    for (int i = 0; i < 8; i++) { acc[i][0] = 0ull; acc[i][1] = 0ull; }

    for (int kc = 0; kc < K; kc += 32) {
#pragma unroll
        for (int it = 0; it < 2; it++) {
            int rr = tid + it * 256;               // 512: 64 o x 8 kq
            int o = rr >> 3, kq = rr & 7;
            float4 w = *(const float4*)&Wp[(long long)o * K + kc + kq * 4];
            *(u64*)&Ws2[(kq * 4 + 0) * GS + o * 2] = pk2(w.x, w.x);
            *(u64*)&Ws2[(kq * 4 + 1) * GS + o * 2] = pk2(w.y, w.y);
            *(u64*)&Ws2[(kq * 4 + 2) * GS + o * 2] = pk2(w.z, w.z);
            *(u64*)&Ws2[(kq * 4 + 3) * GS + o * 2] = pk2(w.w, w.w);
        }
        if (XALN16) {
#pragma unroll
            for (int it = 0; it < 4; it++) {
                int rr = tid + it * 256;           // 1024 quads: 32 k x 32 t4
                int i = rr >> 5, ts = rr & 31;
                *(float4*)&Xs[i * GS + ts * 4] =
                    *(const float4*)&Xp[(long long)(kc + i) * Tt + t0 + ts * 4];
            }
        } else {
#pragma unroll
            for (int it = 0; it < 8; it++) {
                int rr = tid + it * 256;           // 2048 u64: 32 k x 64 t2
                int i = rr >> 6, t2 = rr & 63;
                *(u64*)&Xs[i * GS + t2 * 2] =
                    *(const u64*)&Xp[(long long)(kc + i) * Tt + t0 + t2 * 2];
            }
        }
        __syncthreads();
#pragma unroll 8
        for (int k = 0; k < 32; k++) {
            const u64* xp = (const u64*)&Xs[k * GS + t4 * 4];
            u64 xa = xp[0], xb = xp[1];
            const u64* wp = (const u64*)&Ws2[k * GS + to * 16];   // broadcast
#pragma unroll
            for (int oj = 0; oj < 8; oj++) {
                u64 w = wp[oj];
                fma2(acc[oj][0], w, xa);
                fma2(acc[oj][1], w, xb);
            }
        }
        __syncthreads();
    }
#pragma unroll
    for (int oj = 0; oj < 8; oj++) {
        long long rb = (long long)(to * 8 + oj) * Tt + t4 * 4;
        *(u64*)&Op[rb]     = acc[oj][0];
        *(u64*)&Op[rb + 2] = acc[oj][1];
    }
}

// ---------------- dist + argmin + gather + qproj + loss partials ----------------
// block = 64 t, 256 threads; scans 4096 codes in chunks of 128.
// thread = 8 t x 4 k; warp <-> one 8-t group, so duplicated E is a broadcast
// smem read; C is one lane-consecutive LDS.128. cbT pre-scaled by -2, acc
// initialized from ||cb_n||^2 -> accumulator IS the score.
static constexpr int SMEM_DIST = (64 * GS + 64 * GS + 128 + 64 + 64) * 4;   // 68608 B

__global__ __launch_bounds__(256) void k_dist(const float* __restrict__ cb,
                                              float* __restrict__ out)
{
    extern __shared__ float sm[];
    float* Es2   = sm;                          // [64 o][132] dup t
    float* Cs    = sm + 64 * GS;                // [64 o][132] chunk of -2*cbT
    float* cbn2s = Cs + 64 * GS;                // [128]
    float* den   = cbn2s + 128;                 // [64]
    int*   scode = (int*)(den + 64);            // [64]
    float* redv  = Cs;                          // overlap (after chunk loop)
    int*   redi  = (int*)(Cs + 2048);

    int b = blockIdx.y, tid = threadIdx.x;
    long long t0 = (long long)blockIdx.x * 64;
    int tx = tid & 31;          // k-slot of 4
    int ty = tid >> 5;          // 0..7 : t-group of 8 (constant per warp)
    const long long xbase = O_XPROJ + (long long)b * (CC * Tt) + t0;

    // stage plain x_proj tile into Cs (free until chunk loop)
#pragma unroll
    for (int it = 0; it < 8; it++) {
        int rr = tid + it * 256;                // 2048 u64: 64 o x 32 t2
        int o = rr >> 5, t2 = rr & 31;
        *(u64*)&Cs[o * GS + t2 * 2] = *(const u64*)&out[xbase + (long long)o * Tt + t2 * 2];
    }
    __syncthreads();
    if (tid < 64) {
        float s = 0.f;
#pragma unroll 8
        for (int o = 0; o < 64; o++) { float v = Cs[o * GS + tid]; s += v * v; }
        den[tid] = fmaxf(__fsqrt_rn(s), 1e-12f);
    }
    __syncthreads();
#pragma unroll
    for (int it = 0; it < 8; it++) {
        int rr = tid + it * 256;
        int o = rr >> 5, t2 = rr & 31;
        float2 v = upk2(*(const u64*)&Cs[o * GS + t2 * 2]);
        float e0 = __fdiv_rn(v.x, den[t2 * 2]);
        float e1 = __fdiv_rn(v.y, den[t2 * 2 + 1]);
        *(u64*)&Es2[o * GS + t2 * 4]     = pk2(e0, e0);
        *(u64*)&Es2[o * GS + t2 * 4 + 2] = pk2(e1, e1);
    }

    float bval[8]; int bidx[8];
#pragma unroll
    for (int i = 0; i < 8; i++) { bval[i] = 3.4028235e38f; bidx[i] = 0; }

    for (int ch = 0; ch < 32; ch++) {
        int kc0 = ch * 128;
        __syncthreads();
#pragma unroll
        for (int it = 0; it < 8; it++) {
            int rr = tid + it * 256;            // 2048 quads: 64 o x 32 k4
            int o = rr >> 5, k4 = rr & 31;
            *(float4*)&Cs[o * GS + k4 * 4] = *(const float4*)&g_cbT[o * Kk + kc0 + k4 * 4];
        }
        if (tid < 128) cbn2s[tid] = g_cbn2[kc0 + tid];
        __syncthreads();

        const u64* ip = (const u64*)&cbn2s[tx * 4];
        u64 i0 = ip[0], i1 = ip[1];
        u64 acc[8][2];
#pragma unroll
        for (int tl = 0; tl < 8; tl++) { acc[tl][0] = i0; acc[tl][1] = i1; }

#pragma unroll 8
        for (int o = 0; o < 64; o++) {
            const u64* cp = (const u64*)&Cs[o * GS + tx * 4];
            u64 c0 = cp[0], c1 = cp[1];
            const u64* ep = (const u64*)&Es2[o * GS + ty * 16];   // broadcast
#pragma unroll
            for (int tl = 0; tl < 8; tl++) {
                u64 e = ep[tl];
                fma2(acc[tl][0], e, c0);
                fma2(acc[tl][1], e, c1);
            }
        }
#pragma unroll
        for (int tl = 0; tl < 8; tl++) {
#pragma unroll
            for (int j = 0; j < 2; j++) {
                float2 d = upk2(acc[tl][j]);
                int kg = kc0 + tx * 4 + j * 2;
                if (d.x < bval[tl]) { bval[tl] = d.x; bidx[tl] = kg; }
                if (d.y < bval[tl]) { bval[tl] = d.y; bidx[tl] = kg + 1; }
            }
        }
    }
    __syncthreads();                            // Cs reads done -> redv/redi overlap safe
#pragma unroll
    for (int tl = 0; tl < 8; tl++) {
        redv[(ty * 8 + tl) * 32 + tx] = bval[tl];
        redi[(ty * 8 + tl) * 32 + tx] = bidx[tl];
    }
    __syncthreads();
    if (tid < 64) {
        float bv = 3.4028235e38f; int bi = 0x7fffffff;
#pragma unroll
        for (int j = 0; j < 32; j++) {
            float v = redv[tid * 32 + j]; int i = redi[tid * 32 + j];
            if (v < bv || (v == bv && i < bi)) { bv = v; bi = i; }
        }
        scode[tid] = bi;
        out[O_CODES + (long long)b * Tt + t0 + tid] = (float)bi;
    }
    __syncthreads();

    // gather q, write quantized_proj = xp + (q - xp), accumulate loss
    {
        int t = tid & 63, og = tid >> 6;        // og 0..3 -> 16 o each
        int code = scode[t];
        const float* cbrow = cb + (long long)code * CC + og * 16;
        long long xb2 = O_XPROJ + (long long)b * (CC * Tt) + t0 + t;
        long long qb2 = O_QPROJ + (long long)b * (CC * Tt) + t0 + t;
        float ls = 0.f;
#pragma unroll
        for (int j = 0; j < 16; j++) {
            long long ro = (long long)(og * 16 + j) * Tt;
            float xp = out[xb2 + ro];
            float q  = cbrow[j];
            float d  = q - xp;
            out[qb2 + ro] = xp + d;
            ls += d * d;
        }
        __syncthreads();
        redv[tid] = ls; __syncthreads();
        for (int off = 128; off > 0; off >>= 1) {
            if (tid < off) redv[tid] += redv[tid + off];
            __syncthreads();
        }
        if (tid == 0) g_lpart[blockIdx.y * gridDim.x + blockIdx.x] = (double)redv[0];
    }
}

// ---------------- final loss reduction ----------------
__global__ __launch_bounds__(512) void k_loss(float* __restrict__ out)
{
    __shared__ double sb[512];
    int tid = threadIdx.x;
    sb[tid] = g_lpart[tid];
    __syncthreads();
    for (int off = 256; off > 0; off >>= 1) {
        if (tid < off) sb[tid] += sb[tid + off];
        __syncthreads();
    }
    if (tid == 0) {
        float l = (float)(sb[0] / (double)(16.0 * 64.0 * 2048.0));
        out[O_CBL] = l;
        out[O_CML] = l;
    }
}

extern "C" void kernel_launch(void* const* d_in, const int* in_sizes, int n_in,
                              void* d_out, int out_size) {
    (void)in_sizes; (void)n_in; (void)out_size;
    const float* x    = (const float*)d_in[0];
    const float* v_in = (const float*)d_in[1];
    const float* g_in = (const float*)d_in[2];
    const float* v_out= (const float*)d_in[3];
    const float* g_out= (const float*)d_in[4];
    const float* cb   = (const float*)d_in[5];
    float* out = (float*)d_out;

    cudaFuncSetAttribute(k_dist, cudaFuncAttributeMaxDynamicSharedMemorySize, SMEM_DIST);

    k_prep_win<<<64, 256>>>(v_in, g_in);
    k_prep_wout<<<128, 256>>>(v_out, g_out);
    k_prep_cb<<<512, 256>>>(cb);

    float* winp; cudaGetSymbolAddress((void**)&winp, g_Win);
    float* woutp; cudaGetSymbolAddress((void**)&woutp, g_Wout);

    // x_proj = W_in @ x : grid 16 t-tiles x 16 b
    k_gemm<true><<<dim3(16, 16, 1), 256>>>(winp, CE, 0ll,
                                           x, (long long)CE * Tt,
                                           out + O_XPROJ, (long long)CC * Tt, 0ll);

    // codes / qproj / loss partials : 32 t-tiles x 16 b
    k_dist<<<dim3(32, 16), 256, SMEM_DIST>>>(cb, out);
    k_loss<<<1, 512>>>(out);

    // quantized = W_out @ quantized_proj : 16 t x 16 b x 16 o-blocks (64 rows each)
    k_gemm<false><<<dim3(16, 16, 16), 256>>>(woutp, CC, (long long)64 * CC,
                                             out + O_QPROJ, (long long)CC * Tt,
                                             out + O_QUANT, (long long)CE * Tt, (long long)64 * Tt);
}

// round 8
// speedup vs baseline: 1.1455x; 1.0845x over previous
#include <cuda_runtime.h>

typedef unsigned long long u64;

static constexpr int Bb = 16;
static constexpr int CE = 1024;
static constexpr int Tt = 2048;
static constexpr int CC = 64;
static constexpr int Kk = 4096;

static constexpr long long O_CODES = 0;
static constexpr long long O_QUANT = 32768;
static constexpr long long N_QUANT = (long long)Bb * CE * Tt;    // 33554432
static constexpr long long O_CBL   = O_QUANT + N_QUANT;           // 33587200
static constexpr long long O_CML   = O_CBL + 1;
static constexpr long long O_XPROJ = O_CML + 1;                   // 33587202 (even -> 8B aligned)
static constexpr long long N_XP    = (long long)Bb * CC * Tt;     // 2097152
static constexpr long long O_QPROJ = O_XPROJ + N_XP;              // 35684354 (even)

// scratch (static device globals; no runtime allocation)
__device__ __align__(16) float  g_WdI[CE * 128];        // W_in dup, k-major: [k][o*2]
__device__ __align__(16) float  g_WdO[16 * CC * 128];   // W_out dup, per o-block: [z][k][o*2]
__device__ __align__(16) float  g_cbT[CC * Kk];         // (-2 * normalized codebook) [o][k]
__device__ __align__(16) float  g_cbn2[Kk];             // ||cb_n||^2
__device__ double g_lpart[512];

__device__ __forceinline__ u64 pk2(float lo, float hi) {
    u64 r; asm("mov.b64 %0, {%1, %2};" : "=l"(r) : "f"(lo), "f"(hi)); return r;
}
__device__ __forceinline__ float2 upk2(u64 v) {
    float2 r; asm("mov.b64 {%0, %1}, %2;" : "=f"(r.x), "=f"(r.y) : "l"(v)); return r;
}
__device__ __forceinline__ void fma2(u64 &d, u64 a, u64 b) {
    asm("fma.rn.f32x2 %0, %1, %2, %0;" : "+l"(d) : "l"(a), "l"(b));
}
__device__ __forceinline__ unsigned s2u(const void* p) {
    return (unsigned)__cvta_generic_to_shared(p);
}
__device__ __forceinline__ void cp16(unsigned s, const void* g) {
    asm volatile("cp.async.cg.shared.global [%0], [%1], 16;" :: "r"(s), "l"(g));
}
__device__ __forceinline__ void cp8(unsigned s, const void* g) {
    asm volatile("cp.async.ca.shared.global [%0], [%1], 8;" :: "r"(s), "l"(g));
}
__device__ __forceinline__ void cpcommit() { asm volatile("cp.async.commit_group;"); }
__device__ __forceinline__ void cpwait1()  { asm volatile("cp.async.wait_group 1;"); }

// ---------------- prep: weight-norm W_in -> dup k-major g_WdI ----------------
__global__ __launch_bounds__(256) void k_prep_win(const float* __restrict__ v_in,
                                                  const float* __restrict__ g_in)
{
    __shared__ float sb[256];
    __shared__ float snorm;
    int o = blockIdx.x, tid = threadIdx.x;
    float s = 0.f;
#pragma unroll
    for (int j = 0; j < 4; j++) { float v = v_in[o * CE + tid + j * 256]; s += v * v; }
    sb[tid] = s; __syncthreads();
    for (int off = 128; off > 0; off >>= 1) { if (tid < off) sb[tid] += sb[tid + off]; __syncthreads(); }
    if (tid == 0) snorm = __fsqrt_rn(sb[0]);
    __syncthreads();
    float n = snorm, g = g_in[o];
#pragma unroll
    for (int j = 0; j < 4; j++) {
        int i = tid + j * 256;
        float w = __fdiv_rn(g * v_in[o * CE + i], n);
        *(u64*)&g_WdI[i * 128 + o * 2] = pk2(w, w);
    }
}

// ---------------- prep: weight-norm W_out -> dup per-o-block g_WdO ----------------
__global__ __launch_bounds__(256) void k_prep_wout(const float* __restrict__ v_out,
                                                   const float* __restrict__ g_out)
{
    int gw = (blockIdx.x * 256 + threadIdx.x) >> 5;   // o_global 0..1023
    int l = threadIdx.x & 31;
    float a = v_out[gw * CC + l], b = v_out[gw * CC + l + 32];
    float s = a * a + b * b;
#pragma unroll
    for (int off = 16; off; off >>= 1) s += __shfl_xor_sync(0xffffffffu, s, off);
    float n = __fsqrt_rn(s), g = g_out[gw];
    float wa = __fdiv_rn(g * a, n);
    float wb = __fdiv_rn(g * b, n);
    int z = gw >> 6, o = gw & 63;
    *(u64*)&g_WdO[(z * CC + l)      * 128 + o * 2] = pk2(wa, wa);
    *(u64*)&g_WdO[(z * CC + l + 32) * 128 + o * 2] = pk2(wb, wb);
}

// ---------------- prep: normalize codebook -> (-2x) transposed + ||.||^2 ----------------
__global__ __launch_bounds__(256) void k_prep_cb(const float* __restrict__ cb)
{
    int k = (blockIdx.x * 256 + threadIdx.x) >> 5;
    int l = threadIdx.x & 31;
    float a = cb[k * CC + l], b = cb[k * CC + l + 32];
    float s = a * a + b * b;
#pragma unroll
    for (int off = 16; off; off >>= 1) s += __shfl_xor_sync(0xffffffffu, s, off);
    float n = fmaxf(__fsqrt_rn(s), 1e-12f);
    float ca = __fdiv_rn(a, n), cbv = __fdiv_rn(b, n);
    g_cbT[l * Kk + k]        = -2.f * ca;
    g_cbT[(l + 32) * Kk + k] = -2.f * cbv;
    float s2 = ca * ca + cbv * cbv;
#pragma unroll
    for (int off = 16; off; off >>= 1) s2 += __shfl_xor_sync(0xffffffffu, s2, off);
    if (l == 0) g_cbn2[k] = s2;
}

// ---------------- Out[64 x 128t] = W[64 x K] @ X[K x 128t], 2-stage cp.async ----------------
// 256 threads, thread = 8 o x 4 t; warp <-> o-group so W (pre-dup in global) is a
// broadcast smem read; X is one lane-consecutive LDS.128 per k.
static constexpr int GS = 132;
static constexpr int STG = 32 * GS;                       // floats per stage tile
static constexpr int SMEM_GEMM = 4 * STG * 4;             // 67584 B

template<bool XALN16>
__global__ __launch_bounds__(256) void k_gemm(const float* __restrict__ Wd, int K, long long WzS,
                                              const float* __restrict__ X, long long XyS,
                                              float* __restrict__ O, long long OyS, long long OzS)
{
    extern __shared__ float sm[];
    float* XsB = sm;              // [2][STG]
    float* WsB = sm + 2 * STG;    // [2][STG]
    int tid = threadIdx.x;
    int to = tid >> 5;            // o-group (constant per warp)
    int t4 = tid & 31;            // t-slot of 4
    const float* Wp = Wd + (long long)blockIdx.z * WzS;
    const float* Xp = X + (long long)blockIdx.y * XyS + (long long)blockIdx.x * 128;
    float* Op = O + (long long)blockIdx.y * OyS + (long long)blockIdx.z * OzS + (long long)blockIdx.x * 128;

    auto load = [&](int st, int kc) {
        float* Ws = WsB + st * STG;
        float* Xs = XsB + st * STG;
#pragma unroll
        for (int it = 0; it < 4; it++) {
            int rr = tid + it * 256;             // 1024: 32 k x 32 quads
            int k = rr >> 5, q = rr & 31;
            cp16(s2u(&Ws[k * GS + q * 4]), &Wp[(long long)(kc + k) * 128 + q * 4]);
        }
        if (XALN16) {
#pragma unroll
            for (int it = 0; it < 4; it++) {
                int rr = tid + it * 256;
                int k = rr >> 5, q = rr & 31;
                cp16(s2u(&Xs[k * GS + q * 4]), &Xp[(long long)(kc + k) * Tt + q * 4]);
            }
        } else {
#pragma unroll
            for (int it = 0; it < 8; it++) {
                int rr = tid + it * 256;         // 2048: 32 k x 64 u64
                int k = rr >> 6, q = rr & 63;
                cp8(s2u(&Xs[k * GS + q * 2]), &Xp[(long long)(kc + k) * Tt + q * 2]);
            }
        }
    };

    u64 acc[8][2];
#pragma unroll
    for (int i = 0; i < 8; i++) { acc[i][0] = 0ull; acc[i][1] = 0ull; }

    load(0, 0); cpcommit();
    int nch = K >> 5;
    for (int c = 0; c < nch; c++) {
        if (c + 1 < nch) load((c + 1) & 1, (c + 1) << 5);
        cpcommit();
        cpwait1();
        __syncthreads();
        const float* Xs = XsB + (c & 1) * STG;
        const float* Ws = WsB + (c & 1) * STG;
#pragma unroll 8
        for (int k = 0; k < 32; k++) {
            const u64* xp = (const u64*)&Xs[k * GS + t4 * 4];
            u64 xa = xp[0], xb = xp[1];
            const u64* wp = (const u64*)&Ws[k * GS + to * 16];   // broadcast
#pragma unroll
            for (int oj = 0; oj < 8; oj++) {
                u64 w = wp[oj];
                fma2(acc[oj][0], w, xa);
                fma2(acc[oj][1], w, xb);
            }
        }
        __syncthreads();
    }
#pragma unroll
    for (int oj = 0; oj < 8; oj++) {
        long long rb = (long long)(to * 8 + oj) * Tt + t4 * 4;
        *(u64*)&Op[rb]     = acc[oj][0];
        *(u64*)&Op[rb + 2] = acc[oj][1];
    }
}

// ---------------- dist + argmin + gather + qproj + loss partials ----------------
// block = 64 t, 256 threads; 32 chunks of 128 k, 2-stage cp.async on the
// codebook chunk. thread = 8 t x 4 k; dup-E broadcast, C lane-consecutive.
static constexpr int DST = 64 * GS;                       // 8448 floats per stage
static constexpr int SMEM_DIST = (3 * DST + 2 * 128 + 64 + 64) * 4;   // 102912 B

__global__ __launch_bounds__(256) void k_dist(const float* __restrict__ cb,
                                              float* __restrict__ out)
{
    extern __shared__ float sm[];
    float* Es2   = sm;                          // [64 o][GS] dup t
    float* CsB   = sm + DST;                    // [2][64 o][GS]
    float* cb2   = sm + 3 * DST;                // [2][128]
    float* den   = cb2 + 256;                   // [64]
    int*   scode = (int*)(den + 64);            // [64]
    float* redv  = CsB;                         // overlap after chunk loop
    int*   redi  = (int*)(CsB + 2048);

    int b = blockIdx.y, tid = threadIdx.x;
    long long t0 = (long long)blockIdx.x * 64;
    int tx = tid & 31;          // k-slot of 4
    int ty = tid >> 5;          // t-group of 8 (constant per warp)
    const long long xbase = O_XPROJ + (long long)b * (CC * Tt) + t0;

    // stage plain x_proj tile into Cs stage 0 (free until chunk loop)
#pragma unroll
    for (int it = 0; it < 8; it++) {
        int rr = tid + it * 256;                // 2048 u64: 64 o x 32 t2
        int o = rr >> 5, t2 = rr & 31;
        *(u64*)&CsB[o * GS + t2 * 2] = *(const u64*)&out[xbase + (long long)o * Tt + t2 * 2];
    }
    __syncthreads();
    if (tid < 64) {
        float s = 0.f;
#pragma unroll 8
        for (int o = 0; o < 64; o++) { float v = CsB[o * GS + tid]; s += v * v; }
        den[tid] = fmaxf(__fsqrt_rn(s), 1e-12f);
    }
    __syncthreads();
#pragma unroll
    for (int it = 0; it < 8; it++) {
        int rr = tid + it * 256;
        int o = rr >> 5, t2 = rr & 31;
        float2 v = upk2(*(const u64*)&CsB[o * GS + t2 * 2]);
        float e0 = __fdiv_rn(v.x, den[t2 * 2]);
        float e1 = __fdiv_rn(v.y, den[t2 * 2 + 1]);
        *(u64*)&Es2[o * GS + t2 * 4]     = pk2(e0, e0);
        *(u64*)&Es2[o * GS + t2 * 4 + 2] = pk2(e1, e1);
    }
    __syncthreads();                            // Cs0 reads done before prefetch overwrites

    auto loadc = [&](int st, int kc0) {
        float* Cs = CsB + st * DST;
#pragma unroll
        for (int it = 0; it < 8; it++) {
            int rr = tid + it * 256;            // 2048 quads: 64 o x 32 k4
            int o = rr >> 5, k4 = rr & 31;
            cp16(s2u(&Cs[o * GS + k4 * 4]), &g_cbT[o * Kk + kc0 + k4 * 4]);
        }
        if (tid < 32) cp16(s2u(&cb2[st * 128 + tid * 4]), &g_cbn2[kc0 + tid * 4]);
    };

    float bval[8]; int bidx[8];
#pragma unroll
    for (int i = 0; i < 8; i++) { bval[i] = 3.4028235e38f; bidx[i] = 0; }

    loadc(0, 0); cpcommit();
    for (int ch = 0; ch < 32; ch++) {
        if (ch + 1 < 32) loadc((ch + 1) & 1, (ch + 1) * 128);
        cpcommit();
        cpwait1();
        __syncthreads();
        const float* Cs = CsB + (ch & 1) * DST;
        const float* cbn2s = cb2 + (ch & 1) * 128;
        int kc0 = ch * 128;

        const u64* ip = (const u64*)&cbn2s[tx * 4];
        u64 i0 = ip[0], i1 = ip[1];
        u64 acc[8][2];
#pragma unroll
        for (int tl = 0; tl < 8; tl++) { acc[tl][0] = i0; acc[tl][1] = i1; }

#pragma unroll 8
        for (int o = 0; o < 64; o++) {
            const u64* cp = (const u64*)&Cs[o * GS + tx * 4];
            u64 c0 = cp[0], c1 = cp[1];
            const u64* ep = (const u64*)&Es2[o * GS + ty * 16];   // broadcast
#pragma unroll
            for (int tl = 0; tl < 8; tl++) {
                u64 e = ep[tl];
                fma2(acc[tl][0], e, c0);
                fma2(acc[tl][1], e, c1);
            }
        }
#pragma unroll
        for (int tl = 0; tl < 8; tl++) {
#pragma unroll
            for (int j = 0; j < 2; j++) {
                float2 d = upk2(acc[tl][j]);
                int kg = kc0 + tx * 4 + j * 2;
                if (d.x < bval[tl]) { bval[tl] = d.x; bidx[tl] = kg; }
                if (d.y < bval[tl]) { bval[tl] = d.y; bidx[tl] = kg + 1; }
            }
        }
        __syncthreads();
    }
#pragma unroll
    for (int tl = 0; tl < 8; tl++) {
        redv[(ty * 8 + tl) * 32 + tx] = bval[tl];
        redi[(ty * 8 + tl) * 32 + tx] = bidx[tl];
    }
    __syncthreads();
    if (tid < 64) {
        float bv = 3.4028235e38f; int bi = 0x7fffffff;
#pragma unroll
        for (int j = 0; j < 32; j++) {
            float v = redv[tid * 32 + j]; int i = redi[tid * 32 + j];
            if (v < bv || (v == bv && i < bi)) { bv = v; bi = i; }
        }
        scode[tid] = bi;
        out[O_CODES + (long long)b * Tt + t0 + tid] = (float)bi;
    }
    __syncthreads();

    // gather q, write quantized_proj = xp + (q - xp), accumulate loss
    {
        int t = tid & 63, og = tid >> 6;        // og 0..3 -> 16 o each
        int code = scode[t];
        const float* cbrow = cb + (long long)code * CC + og * 16;
        long long xb2 = O_XPROJ + (long long)b * (CC * Tt) + t0 + t;
        long long qb2 = O_QPROJ + (long long)b * (CC * Tt) + t0 + t;
        float ls = 0.f;
#pragma unroll
        for (int j = 0; j < 16; j++) {
            long long ro = (long long)(og * 16 + j) * Tt;
            float xp = out[xb2 + ro];
            float q  = cbrow[j];
            float d  = q - xp;
            out[qb2 + ro] = xp + d;
            ls += d * d;
        }
        __syncthreads();
        redv[tid] = ls; __syncthreads();
        for (int off = 128; off > 0; off >>= 1) {
            if (tid < off) redv[tid] += redv[tid + off];
            __syncthreads();
        }
        if (tid == 0) g_lpart[blockIdx.y * gridDim.x + blockIdx.x] = (double)redv[0];
    }
}

// ---------------- final loss reduction ----------------
__global__ __launch_bounds__(512) void k_loss(float* __restrict__ out)
{
    __shared__ double sb[512];
    int tid = threadIdx.x;
    sb[tid] = g_lpart[tid];
    __syncthreads();
    for (int off = 256; off > 0; off >>= 1) {
        if (tid < off) sb[tid] += sb[tid + off];
        __syncthreads();
    }
    if (tid == 0) {
        float l = (float)(sb[0] / (double)(16.0 * 64.0 * 2048.0));
        out[O_CBL] = l;
        out[O_CML] = l;
    }
}

extern "C" void kernel_launch(void* const* d_in, const int* in_sizes, int n_in,
                              void* d_out, int out_size) {
    (void)in_sizes; (void)n_in; (void)out_size;
    const float* x    = (const float*)d_in[0];
    const float* v_in = (const float*)d_in[1];
    const float* g_in = (const float*)d_in[2];
    const float* v_out= (const float*)d_in[3];
    const float* g_out= (const float*)d_in[4];
    const float* cb   = (const float*)d_in[5];
    float* out = (float*)d_out;

    cudaFuncSetAttribute(k_gemm<true>,  cudaFuncAttributeMaxDynamicSharedMemorySize, SMEM_GEMM);
    cudaFuncSetAttribute(k_gemm<false>, cudaFuncAttributeMaxDynamicSharedMemorySize, SMEM_GEMM);
    cudaFuncSetAttribute(k_dist, cudaFuncAttributeMaxDynamicSharedMemorySize, SMEM_DIST);

    k_prep_win<<<64, 256>>>(v_in, g_in);
    k_prep_wout<<<128, 256>>>(v_out, g_out);
    k_prep_cb<<<512, 256>>>(cb);

    float* wdi; cudaGetSymbolAddress((void**)&wdi, g_WdI);
    float* wdo; cudaGetSymbolAddress((void**)&wdo, g_WdO);

    // x_proj = W_in @ x : 16 t-tiles x 16 b
    k_gemm<true><<<dim3(16, 16, 1), 256, SMEM_GEMM>>>(wdi, CE, 0ll,
                                                      x, (long long)CE * Tt,
                                                      out + O_XPROJ, (long long)CC * Tt, 0ll);

    // codes / qproj / loss partials : 32 t-tiles x 16 b
    k_dist<<<dim3(32, 16), 256, SMEM_DIST>>>(cb, out);
    k_loss<<<1, 512>>>(out);

    // quantized = W_out @ quantized_proj : 16 t x 16 b x 16 o-blocks (64 rows each)
    k_gemm<false><<<dim3(16, 16, 16), 256, SMEM_GEMM>>>(wdo, CC, (long long)CC * 128,
                                                        out + O_QPROJ, (long long)CC * Tt,
                                                        out + O_QUANT, (long long)CE * Tt, (long long)64 * Tt);
}